// round 4
// baseline (speedup 1.0000x reference)
#include <cuda_runtime.h>
#include <cuda_bf16.h>
#include <math.h>

#define NN 100000
#define EE 1600000
#define DDIM 64
#define GGR 2000

// Scratch (allocation-free rule: __device__ globals)
__device__ float g_a[NN * DDIM];
__device__ float g_b[NN * DDIM];
__device__ float g_gate[NN];
__device__ int   g_deg[NN];
__device__ int   g_rs[NN];
__device__ int   g_pos[EE];
__device__ int   g_csr[EE];
__device__ int   g_total;

// ---------------------------------------------------------------------------
// f32x2 packed-FMA helpers (FFMA2 — PTX only, ptxas won't auto-fuse)
// ---------------------------------------------------------------------------
typedef unsigned long long u64;
__device__ __forceinline__ u64 pack2(float lo, float hi) {
    u64 r; asm("mov.b64 %0, {%1, %2};" : "=l"(r) : "f"(lo), "f"(hi)); return r;
}
__device__ __forceinline__ u64 dup2(float a) {
    u64 r; asm("mov.b64 %0, {%1, %1};" : "=l"(r) : "f"(a)); return r;
}
__device__ __forceinline__ void fma2(u64& d, u64 a, u64 b) {
    asm("fma.rn.f32x2 %0, %1, %2, %0;" : "+l"(d) : "l"(a), "l"(b));
}
__device__ __forceinline__ float2 unpack2(u64 v) {
    float2 f; asm("mov.b64 {%0, %1}, %2;" : "=f"(f.x), "=f"(f.y) : "l"(v)); return f;
}

// ---------------------------------------------------------------------------
// CSR build
// ---------------------------------------------------------------------------
__global__ void k_hist(const int* __restrict__ dst, int* __restrict__ deg,
                       int* __restrict__ pos, int e) {
    int i = blockIdx.x * blockDim.x + threadIdx.x;
    if (i >= e) return;
    pos[i] = atomicAdd(&deg[__ldg(&dst[i])], 1);
}

__global__ void __launch_bounds__(256) k_alloc(
    const int* __restrict__ deg, int* __restrict__ rs, int n) {
    __shared__ int sdata[256];
    __shared__ int base;
    int tx = threadIdx.x;
    int i = blockIdx.x * 256 + tx;
    int d = (i < n) ? deg[i] : 0;
    sdata[tx] = d;
    __syncthreads();
    #pragma unroll
    for (int o = 1; o < 256; o <<= 1) {
        int t = (tx >= o) ? sdata[tx - o] : 0;
        __syncthreads();
        sdata[tx] += t;
        __syncthreads();
    }
    int incl = sdata[tx];
    if (tx == 255) base = atomicAdd(&g_total, incl);
    __syncthreads();
    if (i < n) rs[i] = base + incl - d;
}

__global__ void k_fill(const int* __restrict__ src, const int* __restrict__ dst,
                       const int* __restrict__ pos, const int* __restrict__ rs,
                       int* __restrict__ csr, int e) {
    int i = blockIdx.x * blockDim.x + threadIdx.x;
    if (i >= e) return;
    int d = __ldg(&dst[i]);
    csr[__ldg(&rs[d]) + __ldg(&pos[i])] = __ldg(&src[i]);
}

// ---------------------------------------------------------------------------
// Fused: gather (GIN aggregate) + MLP + LayerNorm for a 64-node tile.
// Block 256 threads (16x16), 4x4 per thread. launch_bounds forces 5 blocks/SM.
// ---------------------------------------------------------------------------
__global__ void __launch_bounds__(256, 5) k_mlp(
    const float* __restrict__ X,
    const int* __restrict__ deg, const int* __restrict__ rs, const int* __restrict__ csr,
    const float* __restrict__ eps, int l,
    const float* __restrict__ W1, const float* __restrict__ B1,
    const float* __restrict__ W2, const float* __restrict__ B2,
    const float* __restrict__ LG, const float* __restrict__ LB,
    float* __restrict__ O, int n) {
    __shared__ __align__(16) float sW[64 * 64];
    __shared__ __align__(16) float sH[64 * 68];   // 68*4B = 272B rows (16B aligned)

    int tid = threadIdx.x;
    int tx = tid & 15, ty = tid >> 4;
    int n0 = blockIdx.x * 64;
    int r0 = ty * 4, c0 = tx * 4;

    // W1 -> smem
    #pragma unroll
    for (int idx = tid * 4; idx < 4096; idx += 1024)
        *(float4*)(&sW[idx]) = *(const float4*)(W1 + idx);

    // gather: warp w handles rows w, w+8, ... (lane owns 2 feature dims),
    // neighbor loop unrolled x4 with independent accumulators (MLP=4)
    {
        int lane = tid & 31, w = tid >> 5;
        float s = 1.0f + __ldg(&eps[l]);
        const float2* X2 = (const float2*)X;
        for (int r = w; r < 64; r += 8) {
            int node = n0 + r;
            float2 a0 = make_float2(0.f, 0.f), a1 = a0, a2 = a0, a3 = a0;
            if (node < n) {
                float2 self = X2[(size_t)node * 32 + lane];
                a0.x = self.x * s; a0.y = self.y * s;
                int start = __ldg(&rs[node]);
                int d = __ldg(&deg[node]);
                int t = 0;
                for (; t + 4 <= d; t += 4) {
                    int j0 = __ldg(&csr[start + t + 0]);
                    int j1 = __ldg(&csr[start + t + 1]);
                    int j2 = __ldg(&csr[start + t + 2]);
                    int j3 = __ldg(&csr[start + t + 3]);
                    float2 v0 = X2[(size_t)j0 * 32 + lane];
                    float2 v1 = X2[(size_t)j1 * 32 + lane];
                    float2 v2 = X2[(size_t)j2 * 32 + lane];
                    float2 v3 = X2[(size_t)j3 * 32 + lane];
                    a0.x += v0.x; a0.y += v0.y;
                    a1.x += v1.x; a1.y += v1.y;
                    a2.x += v2.x; a2.y += v2.y;
                    a3.x += v3.x; a3.y += v3.y;
                }
                for (; t < d; t++) {
                    int j = __ldg(&csr[start + t]);
                    float2 v = X2[(size_t)j * 32 + lane];
                    a0.x += v.x; a0.y += v.y;
                }
                a0.x += a1.x + a2.x + a3.x;
                a0.y += a1.y + a2.y + a3.y;
            }
            ((float2*)(&sH[r * 68]))[lane] = a0;
        }
    }
    __syncthreads();

    // GEMM1: t = h @ W1  (k-blocked x4, float4 LDS for both operands)
    u64 acc[4][2];
    #pragma unroll
    for (int j = 0; j < 4; j++) { acc[j][0] = 0ull; acc[j][1] = 0ull; }
    #pragma unroll 4
    for (int k0 = 0; k0 < 64; k0 += 4) {
        float4 a[4];
        #pragma unroll
        for (int j = 0; j < 4; j++) a[j] = *(float4*)(&sH[(r0 + j) * 68 + k0]);
        #pragma unroll
        for (int kk = 0; kk < 4; kk++) {
            float4 b = *(float4*)(&sW[(k0 + kk) * 64 + c0]);
            u64 b01 = pack2(b.x, b.y), b23 = pack2(b.z, b.w);
            #pragma unroll
            for (int j = 0; j < 4; j++) {
                float av = (kk == 0) ? a[j].x : (kk == 1) ? a[j].y : (kk == 2) ? a[j].z : a[j].w;
                u64 aa = dup2(av);
                fma2(acc[j][0], aa, b01);
                fma2(acc[j][1], aa, b23);
            }
        }
    }
    float4 bb1 = *(const float4*)(B1 + c0);
    __syncthreads();

    // silu -> sH ; reload sW with W2
    #pragma unroll
    for (int j = 0; j < 4; j++) {
        float2 t01 = unpack2(acc[j][0]);
        float2 t23 = unpack2(acc[j][1]);
        float t0 = t01.x + bb1.x, t1 = t01.y + bb1.y;
        float t2 = t23.x + bb1.z, t3 = t23.y + bb1.w;
        float4 o4;
        o4.x = t0 / (1.f + __expf(-t0));
        o4.y = t1 / (1.f + __expf(-t1));
        o4.z = t2 / (1.f + __expf(-t2));
        o4.w = t3 / (1.f + __expf(-t3));
        *(float4*)(&sH[(r0 + j) * 68 + c0]) = o4;
    }
    #pragma unroll
    for (int idx = tid * 4; idx < 4096; idx += 1024)
        *(float4*)(&sW[idx]) = *(const float4*)(W2 + idx);
    __syncthreads();

    // GEMM2: u = silu(t) @ W2
    u64 uacc[4][2];
    #pragma unroll
    for (int j = 0; j < 4; j++) { uacc[j][0] = 0ull; uacc[j][1] = 0ull; }
    #pragma unroll 4
    for (int k0 = 0; k0 < 64; k0 += 4) {
        float4 a[4];
        #pragma unroll
        for (int j = 0; j < 4; j++) a[j] = *(float4*)(&sH[(r0 + j) * 68 + k0]);
        #pragma unroll
        for (int kk = 0; kk < 4; kk++) {
            float4 b = *(float4*)(&sW[(k0 + kk) * 64 + c0]);
            u64 b01 = pack2(b.x, b.y), b23 = pack2(b.z, b.w);
            #pragma unroll
            for (int j = 0; j < 4; j++) {
                float av = (kk == 0) ? a[j].x : (kk == 1) ? a[j].y : (kk == 2) ? a[j].z : a[j].w;
                u64 aa = dup2(av);
                fma2(uacc[j][0], aa, b01);
                fma2(uacc[j][1], aa, b23);
            }
        }
    }
    float4 bb2 = *(const float4*)(B2 + c0);

    // LayerNorm per row (16 tx-lanes per row)
    float4 g4 = *(const float4*)(LG + c0);
    float4 lb4 = *(const float4*)(LB + c0);
    #pragma unroll
    for (int j = 0; j < 4; j++) {
        float2 u01 = unpack2(uacc[j][0]);
        float2 u23 = unpack2(uacc[j][1]);
        float u0 = u01.x + bb2.x, u1 = u01.y + bb2.y;
        float u2 = u23.x + bb2.z, u3 = u23.y + bb2.w;
        float s = u0 + u1 + u2 + u3;
        #pragma unroll
        for (int o = 1; o < 16; o <<= 1) s += __shfl_xor_sync(0xffffffffu, s, o);
        float mu = s * (1.f / 64.f);
        float d0 = u0 - mu, d1 = u1 - mu, d2 = u2 - mu, d3 = u3 - mu;
        float q = d0 * d0 + d1 * d1 + d2 * d2 + d3 * d3;
        #pragma unroll
        for (int o = 1; o < 16; o <<= 1) q += __shfl_xor_sync(0xffffffffu, q, o);
        float rstd = rsqrtf(q * (1.f / 64.f) + 1e-5f);
        int row = n0 + r0 + j;
        if (row < n) {
            float4 o4;
            o4.x = d0 * rstd * g4.x + lb4.x;
            o4.y = d1 * rstd * g4.y + lb4.y;
            o4.z = d2 * rstd * g4.z + lb4.z;
            o4.w = d3 * rstd * g4.w + lb4.w;
            *(float4*)(O + (size_t)row * 64 + c0) = o4;
        }
    }
}

// ---------------------------------------------------------------------------
__global__ void __launch_bounds__(256) k_gate(
    const float* __restrict__ X,
    const float* __restrict__ GW1, const float* __restrict__ GB1,
    const float* __restrict__ GW2, const float* __restrict__ GB2,
    float* __restrict__ gate, int n) {
    __shared__ float sg[64 * 32];
    int tid = threadIdx.x;
    for (int i = tid; i < 64 * 32; i += 256) sg[i] = GW1[i];
    __syncthreads();
    int lane = tid & 31, w = tid >> 5;
    int node = blockIdx.x * 8 + w;
    if (node >= n) return;
    float t = GB1[lane];
    const float* xr = X + (size_t)node * 64;
    #pragma unroll
    for (int k = 0; k < 64; k++) t += xr[k] * sg[k * 32 + lane];
    float sil = t / (1.f + __expf(-t));
    float v = sil * GW2[lane];
    #pragma unroll
    for (int o = 16; o > 0; o >>= 1) v += __shfl_xor_sync(0xffffffffu, v, o);
    if (lane == 0) gate[node] = v + GB2[0];
}

// ---------------------------------------------------------------------------
__global__ void k_pool(const float* __restrict__ X, const float* __restrict__ gate,
                       const int* __restrict__ batch, float* __restrict__ out, int n) {
    int g = blockIdx.x;
    int tid = threadIdx.x;  // 64 threads

    int lo = 0, hi = n;
    while (lo < hi) { int mid = (lo + hi) >> 1; if (batch[mid] < g) lo = mid + 1; else hi = mid; }
    int start = lo;
    lo = start; hi = n;
    while (lo < hi) { int mid = (lo + hi) >> 1; if (batch[mid] < g + 1) lo = mid + 1; else hi = mid; }
    int end = lo;

    if (start >= end) { out[(size_t)g * 64 + tid] = 0.f; return; }

    __shared__ float wred[2];
    float m = -3.402823e38f;
    for (int i = start + tid; i < end; i += 64) m = fmaxf(m, gate[i]);
    #pragma unroll
    for (int o = 16; o > 0; o >>= 1) m = fmaxf(m, __shfl_xor_sync(0xffffffffu, m, o));
    if ((tid & 31) == 0) wred[tid >> 5] = m;
    __syncthreads();
    m = fmaxf(wred[0], wred[1]);
    __syncthreads();
    float s = 0.f;
    for (int i = start + tid; i < end; i += 64) s += __expf(gate[i] - m);
    #pragma unroll
    for (int o = 16; o > 0; o >>= 1) s += __shfl_xor_sync(0xffffffffu, s, o);
    if ((tid & 31) == 0) wred[tid >> 5] = s;
    __syncthreads();
    float inv = 1.f / (wred[0] + wred[1]);

    float acc = 0.f;
    for (int i = start; i < end; i++) {
        float w = __expf(gate[i] - m);
        acc += w * X[(size_t)i * 64 + tid];
    }
    out[(size_t)g * 64 + tid] = acc * inv;
}

// ---------------------------------------------------------------------------
extern "C" void kernel_launch(void* const* d_in, const int* in_sizes, int n_in,
                              void* d_out, int out_size) {
    const float* x   = (const float*)d_in[0];
    const int*   ei  = (const int*)d_in[1];
    const int*   bat = (const int*)d_in[2];
    const float* W1  = (const float*)d_in[3];
    const float* b1  = (const float*)d_in[4];
    const float* W2  = (const float*)d_in[5];
    const float* b2  = (const float*)d_in[6];
    const float* eps = (const float*)d_in[7];
    const float* lng = (const float*)d_in[8];
    const float* lnb = (const float*)d_in[9];
    const float* gw1 = (const float*)d_in[10];
    const float* gb1 = (const float*)d_in[11];
    const float* gw2 = (const float*)d_in[12];
    const float* gb2 = (const float*)d_in[13];
    float* out = (float*)d_out;

    int n = in_sizes[0] / DDIM;
    int e = in_sizes[1] / 2;
    int g = out_size / DDIM;
    const int* src = ei;
    const int* dst = ei + e;

    float *ga, *gb, *ggate;
    int *deg, *rsa, *pos, *csr, *tot;
    cudaGetSymbolAddress((void**)&ga, g_a);
    cudaGetSymbolAddress((void**)&gb, g_b);
    cudaGetSymbolAddress((void**)&ggate, g_gate);
    cudaGetSymbolAddress((void**)&deg, g_deg);
    cudaGetSymbolAddress((void**)&rsa, g_rs);
    cudaGetSymbolAddress((void**)&pos, g_pos);
    cudaGetSymbolAddress((void**)&csr, g_csr);
    cudaGetSymbolAddress((void**)&tot, g_total);

    // CSR build (once per launch)
    cudaMemsetAsync(deg, 0, (size_t)n * sizeof(int));
    cudaMemsetAsync(tot, 0, sizeof(int));
    k_hist<<<(e + 255) / 256, 256>>>(dst, deg, pos, e);
    k_alloc<<<(n + 255) / 256, 256>>>(deg, rsa, n);
    k_fill<<<(e + 255) / 256, 256>>>(src, dst, pos, rsa, csr, e);

    // 3 GIN layers, ping-pong buffers
    const float* in0 = x;  float* out0 = ga;
    int nblk = (n + 63) / 64;
    for (int l = 0; l < 3; l++) {
        k_mlp<<<nblk, 256>>>(in0, deg, rsa, csr, eps, l,
                             W1 + l * 4096, b1 + l * 64,
                             W2 + l * 4096, b2 + l * 64,
                             lng + l * 64, lnb + l * 64, out0, n);
        const float* nin = out0;
        out0 = (out0 == ga) ? gb : ga;
        in0 = nin;
    }
    const float* xf = in0;

    k_gate<<<(n + 7) / 8, 256>>>(xf, gw1, gb1, gw2, gb2, ggate, n);
    k_pool<<<g, 64>>>(xf, ggate, bat, out, n);
}

// round 5
// speedup vs baseline: 1.0644x; 1.0644x over previous
#include <cuda_runtime.h>
#include <cuda_fp16.h>
#include <math.h>

#define NN 100000
#define EE 1600000
#define DDIM 64
#define GGR 2000

// Scratch (allocation-free rule: __device__ globals)
__device__ float  g_a[NN * DDIM];     // final fp32 features
__device__ __half g_ha[NN * DDIM];    // fp16 feature ping
__device__ __half g_hb[NN * DDIM];    // fp16 feature pong
__device__ float  g_gate[NN];
__device__ int    g_deg[NN];
__device__ int    g_rs[NN];
__device__ int    g_pos[EE];
__device__ int    g_csr[EE];
__device__ int    g_total;

// ---------------------------------------------------------------------------
// f32x2 packed-FMA helpers (FFMA2 — PTX only, ptxas won't auto-fuse)
// ---------------------------------------------------------------------------
typedef unsigned long long u64;
__device__ __forceinline__ u64 pack2(float lo, float hi) {
    u64 r; asm("mov.b64 %0, {%1, %2};" : "=l"(r) : "f"(lo), "f"(hi)); return r;
}
__device__ __forceinline__ u64 dup2(float a) {
    u64 r; asm("mov.b64 %0, {%1, %1};" : "=l"(r) : "f"(a)); return r;
}
__device__ __forceinline__ void fma2(u64& d, u64 a, u64 b) {
    asm("fma.rn.f32x2 %0, %1, %2, %0;" : "+l"(d) : "l"(a), "l"(b));
}
__device__ __forceinline__ float2 unpack2(u64 v) {
    float2 f; asm("mov.b64 {%0, %1}, %2;" : "=f"(f.x), "=f"(f.y) : "l"(v)); return f;
}

// ---------------------------------------------------------------------------
// CSR build
// ---------------------------------------------------------------------------
__global__ void k_hist(const int* __restrict__ dst, int* __restrict__ deg,
                       int* __restrict__ pos, int e) {
    int i = blockIdx.x * blockDim.x + threadIdx.x;
    if (i >= e) return;
    pos[i] = atomicAdd(&deg[__ldg(&dst[i])], 1);
}

__global__ void __launch_bounds__(256) k_alloc(
    const int* __restrict__ deg, int* __restrict__ rs, int n) {
    __shared__ int sdata[256];
    __shared__ int base;
    int tx = threadIdx.x;
    int i = blockIdx.x * 256 + tx;
    int d = (i < n) ? deg[i] : 0;
    sdata[tx] = d;
    __syncthreads();
    #pragma unroll
    for (int o = 1; o < 256; o <<= 1) {
        int t = (tx >= o) ? sdata[tx - o] : 0;
        __syncthreads();
        sdata[tx] += t;
        __syncthreads();
    }
    int incl = sdata[tx];
    if (tx == 255) base = atomicAdd(&g_total, incl);
    __syncthreads();
    if (i < n) rs[i] = base + incl - d;
}

__global__ void k_fill(const int* __restrict__ src, const int* __restrict__ dst,
                       const int* __restrict__ pos, const int* __restrict__ rs,
                       int* __restrict__ csr, int e) {
    int i = blockIdx.x * blockDim.x + threadIdx.x;
    if (i >= e) return;
    int d = __ldg(&dst[i]);
    csr[__ldg(&rs[d]) + __ldg(&pos[i])] = __ldg(&src[i]);
}

// fp32 -> fp16 feature conversion (layer-0 input)
__global__ void k_cvt(const float* __restrict__ X, __half* __restrict__ Xh, int total4) {
    int i = blockIdx.x * blockDim.x + threadIdx.x;
    if (i >= total4) return;
    float4 v = ((const float4*)X)[i];
    __half2 p0 = __floats2half2_rn(v.x, v.y);
    __half2 p1 = __floats2half2_rn(v.z, v.w);
    uint2 o; o.x = *(unsigned*)&p0; o.y = *(unsigned*)&p1;
    ((uint2*)Xh)[i] = o;
}

// ---------------------------------------------------------------------------
// Fused: fp16 gather (GIN aggregate, fp32 accumulate) + MLP + LayerNorm.
// Block 256 threads. Gather: half-warp (16 lanes x half4) per row -> one warp
// gathers 2 rows concurrently; neighbor loop unrolled x4.
// ---------------------------------------------------------------------------
__global__ void __launch_bounds__(256, 5) k_mlp(
    const __half* __restrict__ Xh,
    const int* __restrict__ deg, const int* __restrict__ rs, const int* __restrict__ csr,
    const float* __restrict__ eps, int l,
    const float* __restrict__ W1, const float* __restrict__ B1,
    const float* __restrict__ W2, const float* __restrict__ B2,
    const float* __restrict__ LG, const float* __restrict__ LB,
    float* __restrict__ Of, __half* __restrict__ Oh, int n) {
    __shared__ __align__(16) float sW[64 * 64];
    __shared__ __align__(16) float sH[64 * 68];

    int tid = threadIdx.x;
    int tx = tid & 15, ty = tid >> 4;
    int n0 = blockIdx.x * 64;
    int r0 = ty * 4, c0 = tx * 4;

    // W1 -> smem
    #pragma unroll
    for (int idx = tid * 4; idx < 4096; idx += 1024)
        *(float4*)(&sW[idx]) = *(const float4*)(W1 + idx);

    // gather: warp w handles 2 rows at a time (half-warp per row),
    // lane `sub` owns dims sub*4..sub*4+3 (half4 = 8B loads)
    {
        int lane = tid & 31, w = tid >> 5;
        int sub = lane & 15, hw = lane >> 4;
        float se = 1.0f + __ldg(&eps[l]);
        #pragma unroll
        for (int it = 0; it < 4; it++) {
            int r = it * 16 + w * 2 + hw;
            int node = n0 + r;
            float4 A0 = make_float4(0.f, 0.f, 0.f, 0.f), A1 = A0, A2 = A0, A3 = A0;
            if (node < n) {
                uint2 sv = *(const uint2*)(Xh + node * 64 + sub * 4);
                float2 f01 = __half22float2(*(__half2*)&sv.x);
                float2 f23 = __half22float2(*(__half2*)&sv.y);
                A0.x = f01.x * se; A0.y = f01.y * se;
                A0.z = f23.x * se; A0.w = f23.y * se;
                int start = __ldg(&rs[node]);
                int d = __ldg(&deg[node]);
                int t = 0;
                for (; t + 4 <= d; t += 4) {
                    int j0 = __ldg(&csr[start + t + 0]);
                    int j1 = __ldg(&csr[start + t + 1]);
                    int j2 = __ldg(&csr[start + t + 2]);
                    int j3 = __ldg(&csr[start + t + 3]);
                    uint2 v0 = *(const uint2*)(Xh + j0 * 64 + sub * 4);
                    uint2 v1 = *(const uint2*)(Xh + j1 * 64 + sub * 4);
                    uint2 v2 = *(const uint2*)(Xh + j2 * 64 + sub * 4);
                    uint2 v3 = *(const uint2*)(Xh + j3 * 64 + sub * 4);
                    float2 a, b;
                    a = __half22float2(*(__half2*)&v0.x); b = __half22float2(*(__half2*)&v0.y);
                    A0.x += a.x; A0.y += a.y; A0.z += b.x; A0.w += b.y;
                    a = __half22float2(*(__half2*)&v1.x); b = __half22float2(*(__half2*)&v1.y);
                    A1.x += a.x; A1.y += a.y; A1.z += b.x; A1.w += b.y;
                    a = __half22float2(*(__half2*)&v2.x); b = __half22float2(*(__half2*)&v2.y);
                    A2.x += a.x; A2.y += a.y; A2.z += b.x; A2.w += b.y;
                    a = __half22float2(*(__half2*)&v3.x); b = __half22float2(*(__half2*)&v3.y);
                    A3.x += a.x; A3.y += a.y; A3.z += b.x; A3.w += b.y;
                }
                for (; t < d; t++) {
                    int j = __ldg(&csr[start + t]);
                    uint2 v = *(const uint2*)(Xh + j * 64 + sub * 4);
                    float2 a = __half22float2(*(__half2*)&v.x);
                    float2 b = __half22float2(*(__half2*)&v.y);
                    A0.x += a.x; A0.y += a.y; A0.z += b.x; A0.w += b.y;
                }
                A0.x += A1.x + A2.x + A3.x;
                A0.y += A1.y + A2.y + A3.y;
                A0.z += A1.z + A2.z + A3.z;
                A0.w += A1.w + A2.w + A3.w;
            }
            *(float4*)(&sH[r * 68 + sub * 4]) = A0;
        }
    }
    __syncthreads();

    // GEMM1: t = h @ W1  (k-blocked x4, float4 LDS, FFMA2)
    u64 acc[4][2];
    #pragma unroll
    for (int j = 0; j < 4; j++) { acc[j][0] = 0ull; acc[j][1] = 0ull; }
    #pragma unroll 4
    for (int k0 = 0; k0 < 64; k0 += 4) {
        float4 a[4];
        #pragma unroll
        for (int j = 0; j < 4; j++) a[j] = *(float4*)(&sH[(r0 + j) * 68 + k0]);
        #pragma unroll
        for (int kk = 0; kk < 4; kk++) {
            float4 b = *(float4*)(&sW[(k0 + kk) * 64 + c0]);
            u64 b01 = pack2(b.x, b.y), b23 = pack2(b.z, b.w);
            #pragma unroll
            for (int j = 0; j < 4; j++) {
                float av = (kk == 0) ? a[j].x : (kk == 1) ? a[j].y : (kk == 2) ? a[j].z : a[j].w;
                u64 aa = dup2(av);
                fma2(acc[j][0], aa, b01);
                fma2(acc[j][1], aa, b23);
            }
        }
    }
    float4 bb1 = *(const float4*)(B1 + c0);
    __syncthreads();

    // silu -> sH ; reload sW with W2
    #pragma unroll
    for (int j = 0; j < 4; j++) {
        float2 t01 = unpack2(acc[j][0]);
        float2 t23 = unpack2(acc[j][1]);
        float t0 = t01.x + bb1.x, t1 = t01.y + bb1.y;
        float t2 = t23.x + bb1.z, t3 = t23.y + bb1.w;
        float4 o4;
        o4.x = t0 / (1.f + __expf(-t0));
        o4.y = t1 / (1.f + __expf(-t1));
        o4.z = t2 / (1.f + __expf(-t2));
        o4.w = t3 / (1.f + __expf(-t3));
        *(float4*)(&sH[(r0 + j) * 68 + c0]) = o4;
    }
    #pragma unroll
    for (int idx = tid * 4; idx < 4096; idx += 1024)
        *(float4*)(&sW[idx]) = *(const float4*)(W2 + idx);
    __syncthreads();

    // GEMM2: u = silu(t) @ W2
    u64 uacc[4][2];
    #pragma unroll
    for (int j = 0; j < 4; j++) { uacc[j][0] = 0ull; uacc[j][1] = 0ull; }
    #pragma unroll 4
    for (int k0 = 0; k0 < 64; k0 += 4) {
        float4 a[4];
        #pragma unroll
        for (int j = 0; j < 4; j++) a[j] = *(float4*)(&sH[(r0 + j) * 68 + k0]);
        #pragma unroll
        for (int kk = 0; kk < 4; kk++) {
            float4 b = *(float4*)(&sW[(k0 + kk) * 64 + c0]);
            u64 b01 = pack2(b.x, b.y), b23 = pack2(b.z, b.w);
            #pragma unroll
            for (int j = 0; j < 4; j++) {
                float av = (kk == 0) ? a[j].x : (kk == 1) ? a[j].y : (kk == 2) ? a[j].z : a[j].w;
                u64 aa = dup2(av);
                fma2(uacc[j][0], aa, b01);
                fma2(uacc[j][1], aa, b23);
            }
        }
    }
    float4 bb2 = *(const float4*)(B2 + c0);

    // LayerNorm per row (16 tx-lanes per row)
    float4 g4 = *(const float4*)(LG + c0);
    float4 lb4 = *(const float4*)(LB + c0);
    #pragma unroll
    for (int j = 0; j < 4; j++) {
        float2 u01 = unpack2(uacc[j][0]);
        float2 u23 = unpack2(uacc[j][1]);
        float u0 = u01.x + bb2.x, u1 = u01.y + bb2.y;
        float u2 = u23.x + bb2.z, u3 = u23.y + bb2.w;
        float s = u0 + u1 + u2 + u3;
        #pragma unroll
        for (int o = 1; o < 16; o <<= 1) s += __shfl_xor_sync(0xffffffffu, s, o);
        float mu = s * (1.f / 64.f);
        float d0 = u0 - mu, d1 = u1 - mu, d2 = u2 - mu, d3 = u3 - mu;
        float q = d0 * d0 + d1 * d1 + d2 * d2 + d3 * d3;
        #pragma unroll
        for (int o = 1; o < 16; o <<= 1) q += __shfl_xor_sync(0xffffffffu, q, o);
        float rstd = rsqrtf(q * (1.f / 64.f) + 1e-5f);
        int row = n0 + r0 + j;
        if (row < n) {
            float4 o4;
            o4.x = d0 * rstd * g4.x + lb4.x;
            o4.y = d1 * rstd * g4.y + lb4.y;
            o4.z = d2 * rstd * g4.z + lb4.z;
            o4.w = d3 * rstd * g4.w + lb4.w;
            if (Of) *(float4*)(Of + (size_t)row * 64 + c0) = o4;
            if (Oh) {
                __half2 p0 = __floats2half2_rn(o4.x, o4.y);
                __half2 p1 = __floats2half2_rn(o4.z, o4.w);
                uint2 ho; ho.x = *(unsigned*)&p0; ho.y = *(unsigned*)&p1;
                *(uint2*)(Oh + row * 64 + c0) = ho;
            }
        }
    }
}

// ---------------------------------------------------------------------------
__global__ void __launch_bounds__(256) k_gate(
    const float* __restrict__ X,
    const float* __restrict__ GW1, const float* __restrict__ GB1,
    const float* __restrict__ GW2, const float* __restrict__ GB2,
    float* __restrict__ gate, int n) {
    __shared__ float sg[64 * 32];
    int tid = threadIdx.x;
    for (int i = tid; i < 64 * 32; i += 256) sg[i] = GW1[i];
    __syncthreads();
    int lane = tid & 31, w = tid >> 5;
    int node = blockIdx.x * 8 + w;
    if (node >= n) return;
    float t = GB1[lane];
    const float* xr = X + (size_t)node * 64;
    #pragma unroll
    for (int k = 0; k < 64; k++) t += xr[k] * sg[k * 32 + lane];
    float sil = t / (1.f + __expf(-t));
    float v = sil * GW2[lane];
    #pragma unroll
    for (int o = 16; o > 0; o >>= 1) v += __shfl_xor_sync(0xffffffffu, v, o);
    if (lane == 0) gate[node] = v + GB2[0];
}

// ---------------------------------------------------------------------------
// Per-graph softmax pool; weights staged in smem per 128-node chunk.
// ---------------------------------------------------------------------------
__global__ void k_pool(const float* __restrict__ X, const float* __restrict__ gate,
                       const int* __restrict__ batch, float* __restrict__ out, int n) {
    int g = blockIdx.x;
    int tid = threadIdx.x;  // 64 threads

    int lo = 0, hi = n;
    while (lo < hi) { int mid = (lo + hi) >> 1; if (batch[mid] < g) lo = mid + 1; else hi = mid; }
    int start = lo;
    lo = start; hi = n;
    while (lo < hi) { int mid = (lo + hi) >> 1; if (batch[mid] < g + 1) lo = mid + 1; else hi = mid; }
    int end = lo;

    if (start >= end) { out[(size_t)g * 64 + tid] = 0.f; return; }

    __shared__ float wred[2];
    __shared__ float sw[128];
    float m = -3.402823e38f;
    for (int i = start + tid; i < end; i += 64) m = fmaxf(m, gate[i]);
    #pragma unroll
    for (int o = 16; o > 0; o >>= 1) m = fmaxf(m, __shfl_xor_sync(0xffffffffu, m, o));
    if ((tid & 31) == 0) wred[tid >> 5] = m;
    __syncthreads();
    m = fmaxf(wred[0], wred[1]);
    __syncthreads();
    float s = 0.f;
    for (int i = start + tid; i < end; i += 64) s += __expf(gate[i] - m);
    #pragma unroll
    for (int o = 16; o > 0; o >>= 1) s += __shfl_xor_sync(0xffffffffu, s, o);
    if ((tid & 31) == 0) wred[tid >> 5] = s;
    __syncthreads();
    float inv = 1.f / (wred[0] + wred[1]);

    float acc = 0.f;
    for (int chunk = start; chunk < end; chunk += 128) {
        int cnt = min(128, end - chunk);
        __syncthreads();
        for (int i = tid; i < cnt; i += 64) sw[i] = __expf(gate[chunk + i] - m);
        __syncthreads();
        for (int k = 0; k < cnt; k++)
            acc += sw[k] * X[(size_t)(chunk + k) * 64 + tid];
    }
    out[(size_t)g * 64 + tid] = acc * inv;
}

// ---------------------------------------------------------------------------
extern "C" void kernel_launch(void* const* d_in, const int* in_sizes, int n_in,
                              void* d_out, int out_size) {
    const float* x   = (const float*)d_in[0];
    const int*   ei  = (const int*)d_in[1];
    const int*   bat = (const int*)d_in[2];
    const float* W1  = (const float*)d_in[3];
    const float* b1  = (const float*)d_in[4];
    const float* W2  = (const float*)d_in[5];
    const float* b2  = (const float*)d_in[6];
    const float* eps = (const float*)d_in[7];
    const float* lng = (const float*)d_in[8];
    const float* lnb = (const float*)d_in[9];
    const float* gw1 = (const float*)d_in[10];
    const float* gb1 = (const float*)d_in[11];
    const float* gw2 = (const float*)d_in[12];
    const float* gb2 = (const float*)d_in[13];
    float* out = (float*)d_out;

    int n = in_sizes[0] / DDIM;
    int e = in_sizes[1] / 2;
    int g = out_size / DDIM;
    const int* src = ei;
    const int* dst = ei + e;

    float *ga, *ggate;
    __half *ha, *hb;
    int *deg, *rsa, *pos, *csr, *tot;
    cudaGetSymbolAddress((void**)&ga, g_a);
    cudaGetSymbolAddress((void**)&ha, g_ha);
    cudaGetSymbolAddress((void**)&hb, g_hb);
    cudaGetSymbolAddress((void**)&ggate, g_gate);
    cudaGetSymbolAddress((void**)&deg, g_deg);
    cudaGetSymbolAddress((void**)&rsa, g_rs);
    cudaGetSymbolAddress((void**)&pos, g_pos);
    cudaGetSymbolAddress((void**)&csr, g_csr);
    cudaGetSymbolAddress((void**)&tot, g_total);

    // CSR build (once per launch)
    cudaMemsetAsync(deg, 0, (size_t)n * sizeof(int));
    cudaMemsetAsync(tot, 0, sizeof(int));
    k_hist<<<(e + 255) / 256, 256>>>(dst, deg, pos, e);
    k_alloc<<<(n + 255) / 256, 256>>>(deg, rsa, n);
    k_fill<<<(e + 255) / 256, 256>>>(src, dst, pos, rsa, csr, e);

    // fp32 input -> fp16 working buffer
    int total4 = n * (DDIM / 4);
    k_cvt<<<(total4 + 255) / 256, 256>>>(x, hb, total4);

    // 3 GIN layers over fp16 feature buffers; last layer emits fp32
    int nblk = (n + 63) / 64;
    k_mlp<<<nblk, 256>>>(hb, deg, rsa, csr, eps, 0,
                         W1, b1, W2, b2, lng, lnb,
                         (float*)nullptr, ha, n);
    k_mlp<<<nblk, 256>>>(ha, deg, rsa, csr, eps, 1,
                         W1 + 4096, b1 + 64, W2 + 4096, b2 + 64,
                         lng + 64, lnb + 64,
                         (float*)nullptr, hb, n);
    k_mlp<<<nblk, 256>>>(hb, deg, rsa, csr, eps, 2,
                         W1 + 8192, b1 + 128, W2 + 8192, b2 + 128,
                         lng + 128, lnb + 128,
                         ga, (__half*)nullptr, n);

    k_gate<<<(n + 7) / 8, 256>>>(ga, gw1, gb1, gw2, gb2, ggate, n);
    k_pool<<<g, 64>>>(ga, ggate, bat, out, n);
}